// round 2
// baseline (speedup 1.0000x reference)
#include <cuda_runtime.h>
#include <cuda_bf16.h>

// Shapes (fixed per problem): b=4096, d=1024, u=32, r=32, n_obs=25, s=64
#define B_DIM 4096
#define D_DIM 1024
#define U_DIM 32
#define R_DIM 32
#define OBS_DIM 25

// ---------------------------------------------------------------------------
// Device scratch (no allocations allowed -> __device__ globals)
// ---------------------------------------------------------------------------
__device__ float g_ut_dt[B_DIM * U_DIM];        // ut * dt                [b, u]
__device__ float g_Wq[D_DIM * D_DIM];           // Wq[j, m*32+r] = N_Q[m,j,r]
__device__ float g_Wp[D_DIM * D_DIM];           // Wp[m*32+r, i] = N_P[m,i,r]
__device__ float g_At[D_DIM * D_DIM];           // At[j, i] = A[i, j]
__device__ float g_Bt[U_DIM * D_DIM];           // Bt[m, i] = B[i, m]
__device__ float g_S[B_DIM * D_DIM];            // S[b, m*32+r] = t[b,m,r]*ut_dt[b,m]

// ---------------------------------------------------------------------------
// Prep kernels
// ---------------------------------------------------------------------------
__global__ void prep_ut_dt(const float* __restrict__ ut, const float* __restrict__ dt) {
    int idx = blockIdx.x * 256 + threadIdx.x;
    if (idx < B_DIM * U_DIM) g_ut_dt[idx] = ut[idx] * dt[0];
}

// Wq[j*1024 + (m*32+r)] = NQ[m*32768 + j*32 + r]
__global__ void prep_wq(const float* __restrict__ NQ) {
    int idx = blockIdx.x * 256 + threadIdx.x;   // 1M elements
    int j = idx >> 10;
    int cc = idx & 1023;
    int m = cc >> 5;
    int r = cc & 31;
    g_Wq[idx] = NQ[m * (D_DIM * R_DIM) + j * R_DIM + r];
}

// Wp[(m*32+r)*1024 + i] = NP[m*32768 + i*32 + r]  (tiled transpose per m)
__global__ void prep_wp(const float* __restrict__ NP) {
    __shared__ float t[32][33];
    int m = blockIdx.y;
    int i0 = blockIdx.x * 32;
    t[threadIdx.y][threadIdx.x] =
        NP[m * (D_DIM * R_DIM) + (i0 + threadIdx.y) * R_DIM + threadIdx.x];
    __syncthreads();
    g_Wp[(m * 32 + threadIdx.y) * D_DIM + i0 + threadIdx.x] = t[threadIdx.x][threadIdx.y];
}

// At[j, i] = A[i, j]
__global__ void prep_at(const float* __restrict__ A) {
    __shared__ float t[32][33];
    int i0 = blockIdx.x * 32, j0 = blockIdx.y * 32;
    t[threadIdx.y][threadIdx.x] = A[(i0 + threadIdx.y) * D_DIM + j0 + threadIdx.x];
    __syncthreads();
    g_At[(j0 + threadIdx.y) * D_DIM + i0 + threadIdx.x] = t[threadIdx.x][threadIdx.y];
}

// Bt[m, i] = B[i, m]
__global__ void prep_bt(const float* __restrict__ Bb) {
    __shared__ float t[32][33];
    int i0 = blockIdx.x * 32;
    t[threadIdx.y][threadIdx.x] = Bb[(i0 + threadIdx.y) * U_DIM + threadIdx.x];
    __syncthreads();
    g_Bt[threadIdx.y * D_DIM + i0 + threadIdx.x] = t[threadIdx.x][threadIdx.y];
}

// ---------------------------------------------------------------------------
// Tiled fp32 GEMM: 128x128 block tile, 8x8 per thread, BK=8, 256 threads,
// double-buffered smem. A row-major [M,K] (lda), B row-major [K,N] (ldb).
// ---------------------------------------------------------------------------
struct TileCtx {
    int ar, ac;   // A-tile load: row 0..127, col {0,4}
    int bkr, bc;  // B-tile load: k-row 0..7, col 0..124 step 4
    int m0, n0;   // micro-tile origin
};

__device__ __forceinline__ void run_seg(
    const float* __restrict__ A, int lda,
    const float* __restrict__ B, int ldb, int K,
    float (*As)[8][128], float (*Bs)[8][128],
    float (&acc)[8][8], const TileCtx& c)
{
    int buf = 0;
    // prologue: stage k0 = 0
    {
        float4 av = *(const float4*)(A + c.ar * lda + c.ac);
        float4 bv = *(const float4*)(B + c.bkr * ldb + c.bc);
        As[0][c.ac + 0][c.ar] = av.x;
        As[0][c.ac + 1][c.ar] = av.y;
        As[0][c.ac + 2][c.ar] = av.z;
        As[0][c.ac + 3][c.ar] = av.w;
        *(float4*)&Bs[0][c.bkr][c.bc] = bv;
    }
    __syncthreads();

    for (int k0 = 8; k0 <= K; k0 += 8) {
        const bool more = (k0 < K);
        float4 av, bv;
        if (more) {
            av = *(const float4*)(A + c.ar * lda + k0 + c.ac);
            bv = *(const float4*)(B + (k0 + c.bkr) * ldb + c.bc);
        }
#pragma unroll
        for (int kk = 0; kk < 8; ++kk) {
            float a[8], b[8];
            *(float4*)&a[0] = *(const float4*)&As[buf][kk][c.m0];
            *(float4*)&a[4] = *(const float4*)&As[buf][kk][c.m0 + 4];
            *(float4*)&b[0] = *(const float4*)&Bs[buf][kk][c.n0];
            *(float4*)&b[4] = *(const float4*)&Bs[buf][kk][c.n0 + 4];
#pragma unroll
            for (int i = 0; i < 8; ++i)
#pragma unroll
                for (int j = 0; j < 8; ++j)
                    acc[i][j] = fmaf(a[i], b[j], acc[i][j]);
        }
        if (more) {
            int nb = buf ^ 1;
            As[nb][c.ac + 0][c.ar] = av.x;
            As[nb][c.ac + 1][c.ar] = av.y;
            As[nb][c.ac + 2][c.ar] = av.z;
            As[nb][c.ac + 3][c.ar] = av.w;
            *(float4*)&Bs[nb][c.bkr][c.bc] = bv;
            buf = nb;
        }
        __syncthreads();
    }
}

__device__ __forceinline__ TileCtx make_ctx(int tid) {
    TileCtx c;
    c.ar = tid >> 1;
    c.ac = (tid & 1) * 4;
    c.bkr = tid >> 5;
    c.bc = (tid & 31) * 4;
    c.m0 = (tid >> 4) * 8;
    c.n0 = (tid & 15) * 8;
    return c;
}

// GEMM 1: S = (z_dyn @ Wq) scaled by ut_dt[b, col>>5]
__global__ __launch_bounds__(256, 2) void gemm1_kernel(const float* __restrict__ z_dyn)
{
    __shared__ float As[2][8][128];
    __shared__ float Bs[2][8][128];
    const int tid = threadIdx.x;
    const TileCtx c = make_ctx(tid);
    const int brow = blockIdx.y * 128;
    const int bcol = blockIdx.x * 128;

    float acc[8][8];
#pragma unroll
    for (int i = 0; i < 8; ++i)
#pragma unroll
        for (int j = 0; j < 8; ++j) acc[i][j] = 0.f;

    run_seg(z_dyn + brow * D_DIM, D_DIM, g_Wq + bcol, D_DIM, D_DIM, As, Bs, acc, c);

#pragma unroll
    for (int i = 0; i < 8; ++i) {
        const int row = brow + c.m0 + i;
        const float* ud = g_ut_dt + row * U_DIM;
#pragma unroll
        for (int j4 = 0; j4 < 8; j4 += 4) {
            float4 v;
            v.x = acc[i][j4 + 0] * ud[(bcol + c.n0 + j4 + 0) >> 5];
            v.y = acc[i][j4 + 1] * ud[(bcol + c.n0 + j4 + 1) >> 5];
            v.z = acc[i][j4 + 2] * ud[(bcol + c.n0 + j4 + 2) >> 5];
            v.w = acc[i][j4 + 3] * ud[(bcol + c.n0 + j4 + 3) >> 5];
            *(float4*)&g_S[row * D_DIM + bcol + c.n0 + j4] = v;
        }
    }
}

// GEMM 2: Z = z_dyn @ At + S @ Wp + ut_dt @ Bt   -> writes d_out[0 : b*d)
__global__ __launch_bounds__(256, 2) void gemm2_kernel(const float* __restrict__ z_dyn,
                                                       float* __restrict__ out)
{
    __shared__ float As[2][8][128];
    __shared__ float Bs[2][8][128];
    const int tid = threadIdx.x;
    const TileCtx c = make_ctx(tid);
    const int brow = blockIdx.y * 128;
    const int bcol = blockIdx.x * 128;

    float acc[8][8];
#pragma unroll
    for (int i = 0; i < 8; ++i)
#pragma unroll
        for (int j = 0; j < 8; ++j) acc[i][j] = 0.f;

    run_seg(z_dyn + brow * D_DIM, D_DIM, g_At + bcol, D_DIM, D_DIM, As, Bs, acc, c);
    run_seg(g_S + brow * D_DIM, D_DIM, g_Wp + bcol, D_DIM, D_DIM, As, Bs, acc, c);
    run_seg(g_ut_dt + brow * U_DIM, U_DIM, g_Bt + bcol, D_DIM, U_DIM, As, Bs, acc, c);

#pragma unroll
    for (int i = 0; i < 8; ++i) {
        const int row = brow + c.m0 + i;
#pragma unroll
        for (int j4 = 0; j4 < 8; j4 += 4) {
            float4 v;
            v.x = acc[i][j4 + 0];
            v.y = acc[i][j4 + 1];
            v.z = acc[i][j4 + 2];
            v.w = acc[i][j4 + 3];
            *(float4*)&out[row * D_DIM + bcol + c.n0 + j4] = v;
        }
    }
}

// yt = Z @ C^T + ut_dt @ D^T   (4 warps per block, one row per warp)
__global__ __launch_bounds__(128) void yt_kernel(const float* __restrict__ Z,
                                                 const float* __restrict__ C,
                                                 const float* __restrict__ Dm,
                                                 float* __restrict__ yt)
{
    __shared__ float Cs[OBS_DIM][132];
    const int lane = threadIdx.x & 31;
    const int warp = threadIdx.x >> 5;
    const int b = blockIdx.x * 4 + warp;

    float acc[OBS_DIM];
    {
        float ud = g_ut_dt[b * U_DIM + lane];
#pragma unroll
        for (int o = 0; o < OBS_DIM; ++o) acc[o] = ud * Dm[o * U_DIM + lane];
    }

    for (int kt = 0; kt < D_DIM; kt += 128) {
        __syncthreads();
        for (int idx = threadIdx.x; idx < OBS_DIM * 128; idx += 128) {
            int o = idx >> 7, kk = idx & 127;
            Cs[o][kk] = C[o * D_DIM + kt + kk];
        }
        __syncthreads();
        float4 zv = *(const float4*)(Z + b * D_DIM + kt + lane * 4);
#pragma unroll
        for (int o = 0; o < OBS_DIM; ++o) {
            float4 cv = *(const float4*)&Cs[o][lane * 4];
            acc[o] += zv.x * cv.x + zv.y * cv.y + zv.z * cv.z + zv.w * cv.w;
        }
    }

#pragma unroll
    for (int o = 0; o < OBS_DIM; ++o) {
#pragma unroll
        for (int off = 16; off; off >>= 1)
            acc[o] += __shfl_xor_sync(0xffffffffu, acc[o], off);
    }
    if (lane == 0) {
#pragma unroll
        for (int o = 0; o < OBS_DIM; ++o) yt[b * OBS_DIM + o] = acc[o];
    }
}

// ---------------------------------------------------------------------------
// Launch
// ---------------------------------------------------------------------------
extern "C" void kernel_launch(void* const* d_in, const int* in_sizes, int n_in,
                              void* d_out, int out_size) {
    const float* z_dyn = (const float*)d_in[0];
    // d_in[1] = z_static (unused)
    const float* dt = (const float*)d_in[2];
    const float* ut = (const float*)d_in[3];
    const float* A = (const float*)d_in[4];
    const float* Bb = (const float*)d_in[5];
    const float* NP = (const float*)d_in[6];
    const float* NQ = (const float*)d_in[7];
    const float* C = (const float*)d_in[8];
    const float* Dm = (const float*)d_in[9];
    float* out = (float*)d_out;

    prep_ut_dt<<<(B_DIM * U_DIM + 255) / 256, 256>>>(ut, dt);
    prep_wq<<<(D_DIM * D_DIM) / 256, 256>>>(NQ);
    prep_wp<<<dim3(D_DIM / 32, U_DIM), dim3(32, 32)>>>(NP);
    prep_at<<<dim3(D_DIM / 32, D_DIM / 32), dim3(32, 32)>>>(A);
    prep_bt<<<D_DIM / 32, dim3(32, 32)>>>(Bb);

    dim3 grid(D_DIM / 128, B_DIM / 128);   // (8, 32)
    gemm1_kernel<<<grid, 256>>>(z_dyn);
    gemm2_kernel<<<grid, 256>>>(z_dyn, out);

    yt_kernel<<<B_DIM / 4, 128>>>(out, C, Dm, out + B_DIM * D_DIM);
}

// round 5
// speedup vs baseline: 2.1467x; 2.1467x over previous
#include <cuda_runtime.h>
#include <cuda_bf16.h>
#include <cstdint>

// Shapes (fixed per problem): b=4096, d=1024, u=32, r=32, n_obs=25, s=64
#define B_DIM 4096
#define D_DIM 1024
#define U_DIM 32
#define R_DIM 32
#define OBS_DIM 25

// ---------------------------------------------------------------------------
// Device scratch (no allocations allowed -> __device__ globals)
// ---------------------------------------------------------------------------
__device__ float g_ut_dt[B_DIM * U_DIM];        // ut * dt                [b, u]
__device__ float g_Wq[D_DIM * D_DIM];           // Wq[j, m*32+r] = N_Q[m,j,r]
__device__ float g_Wp[D_DIM * D_DIM];           // Wp[m*32+r, i] = N_P[m,i,r]
__device__ float g_At[D_DIM * D_DIM];           // At[j, i] = A[i, j]
__device__ float g_Bt[U_DIM * D_DIM];           // Bt[m, i] = B[i, m]
__device__ float g_S[B_DIM * D_DIM];            // S[b, m*32+r] = t[b,m,r]*ut_dt[b,m]

// ---------------------------------------------------------------------------
// Prep kernels (tiny)
// ---------------------------------------------------------------------------
__global__ void prep_ut_dt(const float* __restrict__ ut, const float* __restrict__ dt) {
    int idx = blockIdx.x * 256 + threadIdx.x;
    if (idx < B_DIM * U_DIM) g_ut_dt[idx] = ut[idx] * dt[0];
}

__global__ void prep_wq(const float* __restrict__ NQ) {
    int idx = blockIdx.x * 256 + threadIdx.x;   // 1M elements
    int j = idx >> 10;
    int cc = idx & 1023;
    int m = cc >> 5;
    int r = cc & 31;
    g_Wq[idx] = NQ[m * (D_DIM * R_DIM) + j * R_DIM + r];
}

__global__ void prep_wp(const float* __restrict__ NP) {
    __shared__ float t[32][33];
    int m = blockIdx.y;
    int i0 = blockIdx.x * 32;
    t[threadIdx.y][threadIdx.x] =
        NP[m * (D_DIM * R_DIM) + (i0 + threadIdx.y) * R_DIM + threadIdx.x];
    __syncthreads();
    g_Wp[(m * 32 + threadIdx.y) * D_DIM + i0 + threadIdx.x] = t[threadIdx.x][threadIdx.y];
}

__global__ void prep_at(const float* __restrict__ A) {
    __shared__ float t[32][33];
    int i0 = blockIdx.x * 32, j0 = blockIdx.y * 32;
    t[threadIdx.y][threadIdx.x] = A[(i0 + threadIdx.y) * D_DIM + j0 + threadIdx.x];
    __syncthreads();
    g_At[(j0 + threadIdx.y) * D_DIM + i0 + threadIdx.x] = t[threadIdx.x][threadIdx.y];
}

__global__ void prep_bt(const float* __restrict__ Bb) {
    __shared__ float t[32][33];
    int i0 = blockIdx.x * 32;
    t[threadIdx.y][threadIdx.x] = Bb[(i0 + threadIdx.y) * U_DIM + threadIdx.x];
    __syncthreads();
    g_Bt[threadIdx.y * D_DIM + i0 + threadIdx.x] = t[threadIdx.x][threadIdx.y];
}

// ---------------------------------------------------------------------------
// TF32 tensor-core GEMM building blocks
// ---------------------------------------------------------------------------
__device__ __forceinline__ uint32_t f2tf32(float x) {
    uint32_t r;
    asm("cvt.rna.tf32.f32 %0, %1;" : "=r"(r) : "f"(x));
    return r;
}

__device__ __forceinline__ void mma_tf32(float (&c)[4], const uint32_t (&a)[4],
                                         const uint32_t (&b)[2]) {
    asm volatile(
        "mma.sync.aligned.m16n8k8.row.col.f32.tf32.tf32.f32 "
        "{%0,%1,%2,%3}, {%4,%5,%6,%7}, {%8,%9}, {%0,%1,%2,%3};"
        : "+f"(c[0]), "+f"(c[1]), "+f"(c[2]), "+f"(c[3])
        : "r"(a[0]), "r"(a[1]), "r"(a[2]), "r"(a[3]), "r"(b[0]), "r"(b[1]));
}

// Smem tiles: [k][m or n] with pitch 136 -> fragment loads conflict-free:
// bank = ((k&3)*8 + (x&31) + 0) mod 32 covers all 32 banks per quad-group.
#define PITCH 136

// One K-segment of C[128,128] += A[M,K](row-major, lda) * B[K,N](row-major, ldb).
// BK=16, double-buffered. 256 threads = 8 warps; warp w owns 32x64 at
// (m0=(w>>1)*32, n0=(w&1)*64); per-warp 2x8 grid of m16n8k8 mma tiles.
__device__ __forceinline__ void mma_seg(
    const float* __restrict__ A, int lda,
    const float* __restrict__ B, int ldb, int K,
    uint32_t (*As)[16][PITCH], uint32_t (*Bs)[16][PITCH],
    float (&acc)[2][8][4])
{
    const int t = threadIdx.x;
    const int lane = t & 31;
    const int w = t >> 5;
    const int m0 = (w >> 1) * 32;
    const int n0 = (w & 1) * 64;
    const int ar = t >> 1;              // A stage: row 0..127
    const int ac = (t & 1) * 8;         // A stage: k-col base {0,8}
    const int bkr = t >> 4;             // B stage: k-row 0..15
    const int bc = (t & 15) * 8;        // B stage: n-col base

    // ---- stage k0 = 0 into buffer 0 ----
    {
        float4 a0 = *(const float4*)(A + ar * lda + ac);
        float4 a1 = *(const float4*)(A + ar * lda + ac + 4);
        float4 b0 = *(const float4*)(B + bkr * ldb + bc);
        float4 b1 = *(const float4*)(B + bkr * ldb + bc + 4);
        As[0][ac + 0][ar] = f2tf32(a0.x); As[0][ac + 1][ar] = f2tf32(a0.y);
        As[0][ac + 2][ar] = f2tf32(a0.z); As[0][ac + 3][ar] = f2tf32(a0.w);
        As[0][ac + 4][ar] = f2tf32(a1.x); As[0][ac + 5][ar] = f2tf32(a1.y);
        As[0][ac + 6][ar] = f2tf32(a1.z); As[0][ac + 7][ar] = f2tf32(a1.w);
        uint4 u0 = { f2tf32(b0.x), f2tf32(b0.y), f2tf32(b0.z), f2tf32(b0.w) };
        uint4 u1 = { f2tf32(b1.x), f2tf32(b1.y), f2tf32(b1.z), f2tf32(b1.w) };
        *(uint4*)&Bs[0][bkr][bc] = u0;
        *(uint4*)&Bs[0][bkr][bc + 4] = u1;
    }
    __syncthreads();

    int buf = 0;
    for (int k0 = 16; k0 <= K; k0 += 16) {
        const bool more = (k0 < K);
        float4 a0, a1, b0, b1;
        if (more) {
            a0 = *(const float4*)(A + ar * lda + k0 + ac);
            a1 = *(const float4*)(A + ar * lda + k0 + ac + 4);
            b0 = *(const float4*)(B + (k0 + bkr) * ldb + bc);
            b1 = *(const float4*)(B + (k0 + bkr) * ldb + bc + 4);
        }

        // ---- compute on `buf`: two k8 sub-steps ----
#pragma unroll
        for (int k8 = 0; k8 < 16; k8 += 8) {
            const int kq = k8 + (lane & 3);
            uint32_t afr[2][4];
#pragma unroll
            for (int mt = 0; mt < 2; ++mt) {
                const int r0 = m0 + mt * 16 + (lane >> 2);
                afr[mt][0] = As[buf][kq][r0];
                afr[mt][1] = As[buf][kq][r0 + 8];
                afr[mt][2] = As[buf][kq + 4][r0];
                afr[mt][3] = As[buf][kq + 4][r0 + 8];
            }
            uint32_t bfr[8][2];
#pragma unroll
            for (int nt = 0; nt < 8; ++nt) {
                const int cc = n0 + nt * 8 + (lane >> 2);
                bfr[nt][0] = Bs[buf][kq][cc];
                bfr[nt][1] = Bs[buf][kq + 4][cc];
            }
#pragma unroll
            for (int mt = 0; mt < 2; ++mt)
#pragma unroll
                for (int nt = 0; nt < 8; ++nt)
                    mma_tf32(acc[mt][nt], afr[mt], bfr[nt]);
        }

        // ---- stage next tile into buf^1 ----
        if (more) {
            const int nb = buf ^ 1;
            As[nb][ac + 0][ar] = f2tf32(a0.x); As[nb][ac + 1][ar] = f2tf32(a0.y);
            As[nb][ac + 2][ar] = f2tf32(a0.z); As[nb][ac + 3][ar] = f2tf32(a0.w);
            As[nb][ac + 4][ar] = f2tf32(a1.x); As[nb][ac + 5][ar] = f2tf32(a1.y);
            As[nb][ac + 6][ar] = f2tf32(a1.z); As[nb][ac + 7][ar] = f2tf32(a1.w);
            uint4 u0 = { f2tf32(b0.x), f2tf32(b0.y), f2tf32(b0.z), f2tf32(b0.w) };
            uint4 u1 = { f2tf32(b1.x), f2tf32(b1.y), f2tf32(b1.z), f2tf32(b1.w) };
            *(uint4*)&Bs[nb][bkr][bc] = u0;
            *(uint4*)&Bs[nb][bkr][bc + 4] = u1;
            buf = nb;
        }
        __syncthreads();
    }
}

// GEMM 1: S = (z_dyn @ Wq) * ut_dt[row, col>>5]
__global__ __launch_bounds__(256, 2) void gemm1_kernel(const float* __restrict__ z_dyn)
{
    __shared__ uint32_t As[2][16][PITCH];
    __shared__ uint32_t Bs[2][16][PITCH];
    const int t = threadIdx.x;
    const int lane = t & 31;
    const int w = t >> 5;
    const int m0 = (w >> 1) * 32;
    const int n0 = (w & 1) * 64;
    const int brow = blockIdx.y * 128;
    const int bcol = blockIdx.x * 128;

    float acc[2][8][4];
#pragma unroll
    for (int mt = 0; mt < 2; ++mt)
#pragma unroll
        for (int nt = 0; nt < 8; ++nt)
#pragma unroll
            for (int i = 0; i < 4; ++i) acc[mt][nt][i] = 0.f;

    mma_seg(z_dyn + brow * D_DIM, D_DIM, g_Wq + bcol, D_DIM, D_DIM, As, Bs, acc);

#pragma unroll
    for (int mt = 0; mt < 2; ++mt) {
        const int r0 = brow + m0 + mt * 16 + (lane >> 2);
#pragma unroll
        for (int nt = 0; nt < 8; ++nt) {
            const int col = bcol + n0 + nt * 8 + (lane & 3) * 2;
            const int g = (bcol + n0 + nt * 8) >> 5;   // m-group for ut_dt scale
            const float s0 = g_ut_dt[r0 * U_DIM + g];
            const float s1 = g_ut_dt[(r0 + 8) * U_DIM + g];
            float2 v0 = { acc[mt][nt][0] * s0, acc[mt][nt][1] * s0 };
            float2 v1 = { acc[mt][nt][2] * s1, acc[mt][nt][3] * s1 };
            *(float2*)&g_S[r0 * D_DIM + col] = v0;
            *(float2*)&g_S[(r0 + 8) * D_DIM + col] = v1;
        }
    }
}

// GEMM 2: Z = z_dyn @ At + S @ Wp + ut_dt @ Bt  -> d_out[0 : b*d)
__global__ __launch_bounds__(256, 2) void gemm2_kernel(const float* __restrict__ z_dyn,
                                                       float* __restrict__ out)
{
    __shared__ uint32_t As[2][16][PITCH];
    __shared__ uint32_t Bs[2][16][PITCH];
    const int t = threadIdx.x;
    const int lane = t & 31;
    const int w = t >> 5;
    const int m0 = (w >> 1) * 32;
    const int n0 = (w & 1) * 64;
    const int brow = blockIdx.y * 128;
    const int bcol = blockIdx.x * 128;

    float acc[2][8][4];
#pragma unroll
    for (int mt = 0; mt < 2; ++mt)
#pragma unroll
        for (int nt = 0; nt < 8; ++nt)
#pragma unroll
            for (int i = 0; i < 4; ++i) acc[mt][nt][i] = 0.f;

    mma_seg(z_dyn + brow * D_DIM, D_DIM, g_At + bcol, D_DIM, D_DIM, As, Bs, acc);
    mma_seg(g_S + brow * D_DIM, D_DIM, g_Wp + bcol, D_DIM, D_DIM, As, Bs, acc);
    mma_seg(g_ut_dt + brow * U_DIM, U_DIM, g_Bt + bcol, D_DIM, U_DIM, As, Bs, acc);

#pragma unroll
    for (int mt = 0; mt < 2; ++mt) {
        const int r0 = brow + m0 + mt * 16 + (lane >> 2);
#pragma unroll
        for (int nt = 0; nt < 8; ++nt) {
            const int col = bcol + n0 + nt * 8 + (lane & 3) * 2;
            float2 v0 = { acc[mt][nt][0], acc[mt][nt][1] };
            float2 v1 = { acc[mt][nt][2], acc[mt][nt][3] };
            *(float2*)&out[r0 * D_DIM + col] = v0;
            *(float2*)&out[(r0 + 8) * D_DIM + col] = v1;
        }
    }
}

// yt = Z @ C^T + ut_dt @ D^T  (exact fp32; 4 warps/block, one row per warp)
__global__ __launch_bounds__(128) void yt_kernel(const float* __restrict__ Z,
                                                 const float* __restrict__ C,
                                                 const float* __restrict__ Dm,
                                                 float* __restrict__ yt)
{
    __shared__ float Cs[OBS_DIM][132];
    const int lane = threadIdx.x & 31;
    const int warp = threadIdx.x >> 5;
    const int b = blockIdx.x * 4 + warp;

    float acc[OBS_DIM];
    {
        float ud = g_ut_dt[b * U_DIM + lane];
#pragma unroll
        for (int o = 0; o < OBS_DIM; ++o) acc[o] = ud * Dm[o * U_DIM + lane];
    }

    for (int kt = 0; kt < D_DIM; kt += 128) {
        __syncthreads();
        for (int idx = threadIdx.x; idx < OBS_DIM * 128; idx += 128) {
            int o = idx >> 7, kk = idx & 127;
            Cs[o][kk] = C[o * D_DIM + kt + kk];
        }
        __syncthreads();
        float4 zv = *(const float4*)(Z + b * D_DIM + kt + lane * 4);
#pragma unroll
        for (int o = 0; o < OBS_DIM; ++o) {
            float4 cv = *(const float4*)&Cs[o][lane * 4];
            acc[o] += zv.x * cv.x + zv.y * cv.y + zv.z * cv.z + zv.w * cv.w;
        }
    }

#pragma unroll
    for (int o = 0; o < OBS_DIM; ++o) {
#pragma unroll
        for (int off = 16; off; off >>= 1)
            acc[o] += __shfl_xor_sync(0xffffffffu, acc[o], off);
    }
    if (lane == 0) {
#pragma unroll
        for (int o = 0; o < OBS_DIM; ++o) yt[b * OBS_DIM + o] = acc[o];
    }
}

// ---------------------------------------------------------------------------
// Launch
// ---------------------------------------------------------------------------
extern "C" void kernel_launch(void* const* d_in, const int* in_sizes, int n_in,
                              void* d_out, int out_size) {
    const float* z_dyn = (const float*)d_in[0];
    // d_in[1] = z_static (unused)
    const float* dt = (const float*)d_in[2];
    const float* ut = (const float*)d_in[3];
    const float* A = (const float*)d_in[4];
    const float* Bb = (const float*)d_in[5];
    const float* NP = (const float*)d_in[6];
    const float* NQ = (const float*)d_in[7];
    const float* C = (const float*)d_in[8];
    const float* Dm = (const float*)d_in[9];
    float* out = (float*)d_out;

    prep_ut_dt<<<(B_DIM * U_DIM + 255) / 256, 256>>>(ut, dt);
    prep_wq<<<(D_DIM * D_DIM) / 256, 256>>>(NQ);
    prep_wp<<<dim3(D_DIM / 32, U_DIM), dim3(32, 32)>>>(NP);
    prep_at<<<dim3(D_DIM / 32, D_DIM / 32), dim3(32, 32)>>>(A);
    prep_bt<<<D_DIM / 32, dim3(32, 32)>>>(Bb);

    dim3 grid(D_DIM / 128, B_DIM / 128);   // (8, 32)
    gemm1_kernel<<<grid, 256>>>(z_dyn);
    gemm2_kernel<<<grid, 256>>>(z_dyn, out);

    yt_kernel<<<B_DIM / 4, 128>>>(out, C, Dm, out + B_DIM * D_DIM);
}

// round 8
// speedup vs baseline: 2.5531x; 1.1893x over previous
#include <cuda_runtime.h>
#include <cstdint>

// Shapes (fixed): b=4096, d=1024, u=32, r=32, n_obs=25
#define B_DIM 4096
#define D_DIM 1024
#define U_DIM 32
#define OBS_DIM 25

// ---------------------------------------------------------------------------
// Device scratch
// ---------------------------------------------------------------------------
__device__ float g_ut_dt[B_DIM * U_DIM];   // ut*dt                          [b, u]
__device__ float g_WqT[D_DIM * D_DIM];     // WqT[n=(m*32+r)][j] = N_Q[m,j,r]
__device__ float g_WpT[D_DIM * D_DIM];     // WpT[i][c=(m*32+r)] = N_P[m,i,r]
__device__ float g_S[B_DIM * D_DIM];       // S[b, m*32+r]

// ---------------------------------------------------------------------------
// Prep kernels
// ---------------------------------------------------------------------------
__global__ void prep_ut_dt(const float* __restrict__ ut, const float* __restrict__ dt) {
    int idx = blockIdx.x * 256 + threadIdx.x;
    if (idx < B_DIM * U_DIM) g_ut_dt[idx] = ut[idx] * dt[0];
}

// g_WqT[(m*32+r)*1024 + j] = NQ[m*32768 + j*32 + r]
__global__ void prep_wqT(const float* __restrict__ NQ) {
    __shared__ float t[32][33];
    int m = blockIdx.y;
    int j0 = blockIdx.x * 32;
    t[threadIdx.y][threadIdx.x] = NQ[m * 32768 + (j0 + threadIdx.y) * 32 + threadIdx.x];
    __syncthreads();
    g_WqT[(m * 32 + threadIdx.y) * D_DIM + j0 + threadIdx.x] = t[threadIdx.x][threadIdx.y];
}

// g_WpT[i*1024 + m*32 + r] = NP[m*32768 + i*32 + r]
__global__ void prep_wpT(const float* __restrict__ NP) {
    int idx = blockIdx.x * 256 + threadIdx.x;   // 1M
    int i = idx >> 10;
    int c = idx & 1023;
    int m = c >> 5;
    int r = c & 31;
    g_WpT[idx] = NP[m * 32768 + i * 32 + r];
}

// ---------------------------------------------------------------------------
// mma.sync tf32 building blocks (sm_80-class features only — safe on sm_100)
// ---------------------------------------------------------------------------
__device__ __forceinline__ uint32_t f2tf32(float x) {
    uint32_t r;
    asm("cvt.rna.tf32.f32 %0, %1;" : "=r"(r) : "f"(x));
    return r;
}
__device__ __forceinline__ uint32_t smem_u32(const void* p) {
    uint32_t a;
    asm("{ .reg .u64 t; cvta.to.shared.u64 t, %1; cvt.u32.u64 %0, t; }" : "=r"(a) : "l"(p));
    return a;
}
__device__ __forceinline__ void mma_tf32(float (&c)[4], const uint32_t (&a)[4],
                                         const uint32_t (&b)[2]) {
    asm volatile(
        "mma.sync.aligned.m16n8k8.row.col.f32.tf32.tf32.f32 "
        "{%0,%1,%2,%3}, {%4,%5,%6,%7}, {%8,%9}, {%0,%1,%2,%3};"
        : "+f"(c[0]), "+f"(c[1]), "+f"(c[2]), "+f"(c[3])
        : "r"(a[0]), "r"(a[1]), "r"(a[2]), "r"(a[3]), "r"(b[0]), "r"(b[1]));
}
__device__ __forceinline__ void ldsm4(uint32_t (&r)[4], uint32_t a) {
    asm volatile("ldmatrix.sync.aligned.m8n8.x4.shared.b16 {%0,%1,%2,%3}, [%4];"
                 : "=r"(r[0]), "=r"(r[1]), "=r"(r[2]), "=r"(r[3]) : "r"(a));
}
__device__ __forceinline__ uint4 cvt4(float4 v) {
    uint4 u = { f2tf32(v.x), f2tf32(v.y), f2tf32(v.z), f2tf32(v.w) };
    return u;
}

// ---------------------------------------------------------------------------
// GEMM: CTA tile 128x256, BK=32, 256 threads = 8 warps (2m x 4n of 64x64).
// Smem rows: [row][32 floats] = 128B, 16B-unit col swizzled by (c16 ^ (row&7)).
// Double buffered: A 2x16KB, B 2x32KB = 96KB dynamic.
// ---------------------------------------------------------------------------
#define A_BYTES 16384
#define B_BYTES 32768
#define SMEM_NEED (2 * (A_BYTES + B_BYTES))

__device__ __forceinline__ void chunk_src_1(int c, const float* z, int brow, int bcol,
                                            const float*& a, int& alda,
                                            const float*& b, int& bldb) {
    a = z + brow * D_DIM + c * 32;      alda = D_DIM;
    b = g_WqT + bcol * D_DIM + c * 32;  bldb = D_DIM;
}
__device__ __forceinline__ void chunk_src_2(int c, const float* z, const float* Ab,
                                            const float* Bb, int brow, int bcol,
                                            const float*& a, int& alda,
                                            const float*& b, int& bldb) {
    if (c < 32)      { a = z + brow * D_DIM + c * 32;          alda = D_DIM;
                       b = Ab + bcol * D_DIM + c * 32;         bldb = D_DIM; }
    else if (c < 64) { a = g_S + brow * D_DIM + (c - 32) * 32; alda = D_DIM;
                       b = g_WpT + bcol * D_DIM + (c - 32) * 32; bldb = D_DIM; }
    else             { a = g_ut_dt + brow * U_DIM;             alda = U_DIM;
                       b = Bb + bcol * U_DIM;                  bldb = U_DIM; }
}

// 6 units/thread: units 0-1 -> A (512 quarter-rows), 2-5 -> B (1024 quarter-rows)
__device__ __forceinline__ void load_units(const float* __restrict__ a, int alda,
                                           const float* __restrict__ b, int bldb,
                                           float4 (&st)[6][2]) {
    const int t = threadIdx.x;
#pragma unroll
    for (int i = 0; i < 2; ++i) {
        int u = t + i * 256;
        const float* p = a + (u >> 2) * alda + (u & 3) * 8;
        st[i][0] = *(const float4*)(p);
        st[i][1] = *(const float4*)(p + 4);
    }
#pragma unroll
    for (int i = 2; i < 6; ++i) {
        int j = t + (i - 2) * 256;
        const float* p = b + (j >> 2) * bldb + (j & 3) * 8;
        st[i][0] = *(const float4*)(p);
        st[i][1] = *(const float4*)(p + 4);
    }
}

__device__ __forceinline__ void store_units(const float4 (&st)[6][2], char* Ab, char* Bb) {
    const int t = threadIdx.x;
#pragma unroll
    for (int i = 0; i < 6; ++i) {
        int row, q;
        char* base;
        if (i < 2) { int u = t + i * 256; row = u >> 2; q = u & 3; base = Ab; }
        else       { int j = t + (i - 2) * 256; row = j >> 2; q = j & 3; base = Bb; }
        float* rp = (float*)(base + row * 128);
        int c0 = (2 * q) ^ (row & 7);
        int c1 = (2 * q + 1) ^ (row & 7);
        *(uint4*)(rp + c0 * 4) = cvt4(st[i][0]);
        *(uint4*)(rp + c1 * 4) = cvt4(st[i][1]);
    }
}

__device__ __forceinline__ void compute_chunk(uint32_t abase, uint32_t bbase,
                                              float (&acc)[4][8][4],
                                              int m0, int n0, int lane) {
    const int e3 = lane & 7;
    const int rA = e3 + ((lane >> 3) & 1) * 8;
    const int hA = lane >> 4;
    const int rB = e3 + ((lane >> 4) & 1) * 8;
    const int hB = (lane >> 3) & 1;
#pragma unroll
    for (int k8 = 0; k8 < 4; ++k8) {
        const int c16b = 2 * k8;
        uint32_t afr[4][4];
#pragma unroll
        for (int mt = 0; mt < 4; ++mt) {
            uint32_t addr = abase + (uint32_t)((m0 + mt * 16 + rA) * 128 +
                                               (((c16b + hA) ^ e3) << 4));
            ldsm4(afr[mt], addr);
        }
        uint32_t bfr[8][2];
#pragma unroll
        for (int p = 0; p < 4; ++p) {
            uint32_t tmp[4];
            uint32_t addr = bbase + (uint32_t)((n0 + p * 16 + rB) * 128 +
                                               (((c16b + hB) ^ e3) << 4));
            ldsm4(tmp, addr);
            bfr[2 * p][0] = tmp[0]; bfr[2 * p][1] = tmp[1];
            bfr[2 * p + 1][0] = tmp[2]; bfr[2 * p + 1][1] = tmp[3];
        }
#pragma unroll
        for (int mt = 0; mt < 4; ++mt)
#pragma unroll
            for (int nt = 0; nt < 8; ++nt)
                mma_tf32(acc[mt][nt], afr[mt], bfr[nt]);
    }
}

template <int MODE>   // 1: GEMM1 (C=32 -> g_S scaled); 2: GEMM2 (C=65 -> out)
__global__ void __launch_bounds__(256, 1) gemm_mma(
    const float* __restrict__ z,
    const float* __restrict__ Ab,
    const float* __restrict__ Bb,
    float* __restrict__ outp)
{
    extern __shared__ char dsm[];
    char* Asm[2] = { dsm, dsm + A_BYTES };
    char* Bsm[2] = { dsm + 2 * A_BYTES, dsm + 2 * A_BYTES + B_BYTES };
    const uint32_t sb = smem_u32(dsm);
    const uint32_t aoff[2] = { sb, sb + A_BYTES };
    const uint32_t boff[2] = { sb + 2 * A_BYTES, sb + 2 * A_BYTES + B_BYTES };

    const int t = threadIdx.x;
    const int lane = t & 31;
    const int w = t >> 5;
    const int m0 = (w >> 2) * 64;
    const int n0 = (w & 3) * 64;
    const int brow = blockIdx.y * 128;
    const int bcol = blockIdx.x * 256;
    const int C = (MODE == 1) ? 32 : 65;

    float acc[4][8][4];
#pragma unroll
    for (int mt = 0; mt < 4; ++mt)
#pragma unroll
        for (int nt = 0; nt < 8; ++nt)
#pragma unroll
            for (int i = 0; i < 4; ++i) acc[mt][nt][i] = 0.f;

    float4 st[6][2];
    const float *a, *b;
    int alda, bldb;

    // prologue: stage chunk 0
    if (MODE == 1) chunk_src_1(0, z, brow, bcol, a, alda, b, bldb);
    else           chunk_src_2(0, z, Ab, Bb, brow, bcol, a, alda, b, bldb);
    load_units(a, alda, b, bldb, st);
    store_units(st, Asm[0], Bsm[0]);
    __syncthreads();

    int buf = 0;
    for (int c = 0; c < C; ++c) {
        const bool more = (c + 1 < C);
        if (more) {
            if (MODE == 1) chunk_src_1(c + 1, z, brow, bcol, a, alda, b, bldb);
            else           chunk_src_2(c + 1, z, Ab, Bb, brow, bcol, a, alda, b, bldb);
            load_units(a, alda, b, bldb, st);
        }
        compute_chunk(aoff[buf], boff[buf], acc, m0, n0, lane);
        if (more) store_units(st, Asm[buf ^ 1], Bsm[buf ^ 1]);
        __syncthreads();
        buf ^= 1;
    }

    // Epilogue (m16n8 C layout: lane -> rows {r, r+8}, col pair 2*(lane&3))
    const int r = lane >> 2;
    const int cp = (lane & 3) * 2;
#pragma unroll
    for (int mt = 0; mt < 4; ++mt) {
        const int row0 = brow + m0 + mt * 16 + r;
        const int row1 = row0 + 8;
#pragma unroll
        for (int nt = 0; nt < 8; ++nt) {
            const int colbase = bcol + n0 + nt * 8;
            const int col = colbase + cp;
            if (MODE == 1) {
                const int g = colbase >> 5;
                const float s0 = g_ut_dt[row0 * U_DIM + g];
                const float s1 = g_ut_dt[row1 * U_DIM + g];
                float2 v0 = { acc[mt][nt][0] * s0, acc[mt][nt][1] * s0 };
                float2 v1 = { acc[mt][nt][2] * s1, acc[mt][nt][3] * s1 };
                *(float2*)&g_S[row0 * D_DIM + col] = v0;
                *(float2*)&g_S[row1 * D_DIM + col] = v1;
            } else {
                float2 v0 = { acc[mt][nt][0], acc[mt][nt][1] };
                float2 v1 = { acc[mt][nt][2], acc[mt][nt][3] };
                *(float2*)&outp[row0 * D_DIM + col] = v0;
                *(float2*)&outp[row1 * D_DIM + col] = v1;
            }
        }
    }
}

// ---------------------------------------------------------------------------
// yt = Z @ C^T + ut_dt @ D^T  (exact fp32)
// ---------------------------------------------------------------------------
__global__ void __launch_bounds__(128) yt_kernel(const float* __restrict__ Z,
                                                 const float* __restrict__ C,
                                                 const float* __restrict__ Dm,
                                                 float* __restrict__ yt)
{
    __shared__ float Cs[OBS_DIM][132];
    const int lane = threadIdx.x & 31;
    const int warp = threadIdx.x >> 5;
    const int b = blockIdx.x * 4 + warp;

    float acc[OBS_DIM];
    {
        float ud = g_ut_dt[b * U_DIM + lane];
#pragma unroll
        for (int o = 0; o < OBS_DIM; ++o) acc[o] = ud * Dm[o * U_DIM + lane];
    }
    for (int kt = 0; kt < D_DIM; kt += 128) {
        __syncthreads();
        for (int idx = threadIdx.x; idx < OBS_DIM * 128; idx += 128) {
            int o = idx >> 7, kk = idx & 127;
            Cs[o][kk] = C[o * D_DIM + kt + kk];
        }
        __syncthreads();
        float4 zv = *(const float4*)(Z + b * D_DIM + kt + lane * 4);
#pragma unroll
        for (int o = 0; o < OBS_DIM; ++o) {
            float4 cv = *(const float4*)&Cs[o][lane * 4];
            acc[o] += zv.x * cv.x + zv.y * cv.y + zv.z * cv.z + zv.w * cv.w;
        }
    }
#pragma unroll
    for (int o = 0; o < OBS_DIM; ++o) {
#pragma unroll
        for (int off = 16; off; off >>= 1)
            acc[o] += __shfl_xor_sync(0xffffffffu, acc[o], off);
    }
    if (lane == 0) {
#pragma unroll
        for (int o = 0; o < OBS_DIM; ++o) yt[b * OBS_DIM + o] = acc[o];
    }
}

// ---------------------------------------------------------------------------
// Launch
// ---------------------------------------------------------------------------
extern "C" void kernel_launch(void* const* d_in, const int* in_sizes, int n_in,
                              void* d_out, int out_size) {
    const float* z_dyn = (const float*)d_in[0];
    // d_in[1] = z_static (unused)
    const float* dt = (const float*)d_in[2];
    const float* ut = (const float*)d_in[3];
    const float* A = (const float*)d_in[4];
    const float* Bb = (const float*)d_in[5];
    const float* NP = (const float*)d_in[6];
    const float* NQ = (const float*)d_in[7];
    const float* C = (const float*)d_in[8];
    const float* Dm = (const float*)d_in[9];
    float* out = (float*)d_out;

    cudaFuncSetAttribute(gemm_mma<1>, cudaFuncAttributeMaxDynamicSharedMemorySize, SMEM_NEED);
    cudaFuncSetAttribute(gemm_mma<2>, cudaFuncAttributeMaxDynamicSharedMemorySize, SMEM_NEED);

    prep_ut_dt<<<(B_DIM * U_DIM + 255) / 256, 256>>>(ut, dt);
    prep_wqT<<<dim3(D_DIM / 32, U_DIM), dim3(32, 32)>>>(NQ);
    prep_wpT<<<(D_DIM * D_DIM) / 256, 256>>>(NP);

    dim3 grid(D_DIM / 256, B_DIM / 128);   // (4, 32) = 128 CTAs
    gemm_mma<1><<<grid, 256, SMEM_NEED>>>(z_dyn, A, Bb, out);
    gemm_mma<2><<<grid, 256, SMEM_NEED>>>(z_dyn, A, Bb, out);

    yt_kernel<<<B_DIM / 4, 128>>>(out, C, Dm, out + B_DIM * D_DIM);
}